// round 14
// baseline (speedup 1.0000x reference)
#include <cuda_runtime.h>
#include <cuda_fp16.h>
#include <stdint.h>

#define B_   32
#define T_   2048
#define D_   256
#define H_   256
#define G_   1024   // 4*H

// Scratch: permuted input-gate preactivations [B,T,1024] fp32 (includes both biases)
__device__ float g_xg[(size_t)B_ * T_ * G_];

// Column permutation used everywhere:
//   stored col n = r*256 + g*64 + jj  <->  original gate row = g*256 + r*64 + jj

// ---------------------------------------------------------------------------
// Phase 1: xg[m][n] = sum_k relu(x[m][k]) * W_ih[orig(n)][k] + b_ih + b_hh
// fp16 mma.sync m16n8k16, fp32 accumulate. CTA tile 128x128, K=256 one-shot.
// ---------------------------------------------------------------------------
#define ASTRIDE 264   // halves per smem row (4-bank shift per row -> conflict free)

__global__ __launch_bounds__(256) void gemm_kernel(const float* __restrict__ x,
                                                   const float* __restrict__ w_ih,
                                                   const float* __restrict__ b_ih,
                                                   const float* __restrict__ b_hh) {
    extern __shared__ half sm[];
    half* As = sm;                    // [128][ASTRIDE]
    half* Bs = sm + 128 * ASTRIDE;    // [128][ASTRIDE]

    int tid = threadIdx.x;
    int n0 = blockIdx.x * 128;
    int m0 = blockIdx.y * 128;

    for (int i = tid; i < 128 * 64; i += 256) {
        int row = i >> 6, c4 = i & 63;
        float4 v = *(const float4*)(x + (size_t)(m0 + row) * 256 + c4 * 4);
        v.x = fmaxf(v.x, 0.f); v.y = fmaxf(v.y, 0.f);
        v.z = fmaxf(v.z, 0.f); v.w = fmaxf(v.w, 0.f);
        *(half2*)(As + row * ASTRIDE + c4 * 4)     = __floats2half2_rn(v.x, v.y);
        *(half2*)(As + row * ASTRIDE + c4 * 4 + 2) = __floats2half2_rn(v.z, v.w);
    }
    for (int i = tid; i < 128 * 64; i += 256) {
        int row = i >> 6, c4 = i & 63;
        int ng = n0 + row;
        int r = ng >> 8, rem = ng & 255, g = rem >> 6, jj = rem & 63;
        int orig = g * 256 + r * 64 + jj;
        float4 v = *(const float4*)(w_ih + (size_t)orig * 256 + c4 * 4);
        *(half2*)(Bs + row * ASTRIDE + c4 * 4)     = __floats2half2_rn(v.x, v.y);
        *(half2*)(Bs + row * ASTRIDE + c4 * 4 + 2) = __floats2half2_rn(v.z, v.w);
    }
    __syncthreads();

    int lane = tid & 31, warp = tid >> 5;
    int wm = warp & 3;
    int wn = warp >> 2;
    int gr = lane >> 2;
    int qc = (lane & 3) * 2;

    float acc[2][8][4];
    #pragma unroll
    for (int a = 0; a < 2; a++)
        #pragma unroll
        for (int b = 0; b < 8; b++)
            #pragma unroll
            for (int c = 0; c < 4; c++) acc[a][b][c] = 0.f;

    #pragma unroll
    for (int k0 = 0; k0 < 256; k0 += 16) {
        uint32_t af[2][4];
        #pragma unroll
        for (int mt = 0; mt < 2; mt++) {
            int rb = wm * 32 + mt * 16 + gr;
            af[mt][0] = *(const uint32_t*)(As + rb * ASTRIDE + k0 + qc);
            af[mt][1] = *(const uint32_t*)(As + (rb + 8) * ASTRIDE + k0 + qc);
            af[mt][2] = *(const uint32_t*)(As + rb * ASTRIDE + k0 + qc + 8);
            af[mt][3] = *(const uint32_t*)(As + (rb + 8) * ASTRIDE + k0 + qc + 8);
        }
        #pragma unroll
        for (int nt = 0; nt < 8; nt++) {
            int nr = wn * 64 + nt * 8 + gr;
            uint32_t b0 = *(const uint32_t*)(Bs + nr * ASTRIDE + k0 + qc);
            uint32_t b1 = *(const uint32_t*)(Bs + nr * ASTRIDE + k0 + qc + 8);
            #pragma unroll
            for (int mt = 0; mt < 2; mt++) {
                asm volatile(
                    "mma.sync.aligned.m16n8k16.row.col.f32.f16.f16.f32 "
                    "{%0,%1,%2,%3}, {%4,%5,%6,%7}, {%8,%9}, {%0,%1,%2,%3};\n"
                    : "+f"(acc[mt][nt][0]), "+f"(acc[mt][nt][1]),
                      "+f"(acc[mt][nt][2]), "+f"(acc[mt][nt][3])
                    : "r"(af[mt][0]), "r"(af[mt][1]), "r"(af[mt][2]), "r"(af[mt][3]),
                      "r"(b0), "r"(b1));
            }
        }
    }

    #pragma unroll
    for (int mt = 0; mt < 2; mt++) {
        #pragma unroll
        for (int nt = 0; nt < 8; nt++) {
            int col = n0 + wn * 64 + nt * 8 + qc;
            int rr = col >> 8, rem = col & 255, gg = rem >> 6, jjc = rem & 63;
            int orig = gg * 256 + rr * 64 + jjc;
            float bv0 = b_ih[orig] + b_hh[orig];
            float bv1 = b_ih[orig + 1] + b_hh[orig + 1];
            int row = m0 + wm * 32 + mt * 16 + gr;
            float2 v0 = {acc[mt][nt][0] + bv0, acc[mt][nt][1] + bv1};
            float2 v1 = {acc[mt][nt][2] + bv0, acc[mt][nt][3] + bv1};
            *(float2*)(g_xg + (size_t)row * G_ + col)       = v0;
            *(float2*)(g_xg + (size_t)(row + 8) * G_ + col) = v1;
        }
    }
}

// ---------------------------------------------------------------------------
// Phase 2: persistent LSTM scan, ZERO bar.sync in the loop.
// One 4-CTA cluster per batch. Quad layout: thread (jj = tid>>2, ks = tid&3)
// computes ALL 4 gates of h-row (r*64+jj) over K-quarter ks -> c/h needs no
// CTA-wide act exchange. Sync = two mbarriers only:
//   lbar: own-slice h, 32 local packed-u32 arrives/step (waited first)
//   rbar: remote slices, 96 remote arrives/step (waited after own-slice FMA)
// Sends are fire-and-forget; nothing in the loop drains them.
// ---------------------------------------------------------------------------
__device__ __forceinline__ uint32_t smem_u32(const void* p) {
    return (uint32_t)__cvta_generic_to_shared(p);
}

__global__ __launch_bounds__(256, 1) __cluster_dims__(4, 1, 1)
void lstm_kernel(const float* __restrict__ w_hh, float* __restrict__ out) {
    __shared__ __align__(16) half hbuf[2][256];   // double-buffered full h (fp16)
    __shared__ __align__(8) unsigned long long lbar;
    __shared__ __align__(8) unsigned long long rbar;

    int tid = threadIdx.x;
    int b = blockIdx.x >> 2;
    int r = blockIdx.x & 3;
    int jj = tid >> 2;       // h index within this CTA's slice (0..63)
    int ks = tid & 3;        // K-quarter within the quad

    // --- weights: w2[(si*4+g)*8 + i] = gate g, slice (r+si)&3,
    //     k = 64*slice + 16*ks + 2i .. +1  (own slice si=0 first) ---
    half2 w2[128];
    #pragma unroll
    for (int si = 0; si < 4; si++) {
        int s = (r + si) & 3;
        #pragma unroll
        for (int g = 0; g < 4; g++) {
            const float2* wp = (const float2*)(
                w_hh + (size_t)(g * 256 + r * 64 + jj) * 256 + s * 64 + ks * 16);
            #pragma unroll
            for (int i = 0; i < 8; i++) {
                float2 v = wp[i];
                w2[(si * 4 + g) * 8 + i] = __floats2half2_rn(v.x, v.y);
            }
        }
    }

    // --- init smem ---
    ((uint32_t*)hbuf)[tid] = 0u;   // both buffers zeroed
    if (tid == 0) {
        asm volatile("mbarrier.init.shared.b64 [%0], %1;"
                     :: "r"(smem_u32(&lbar)), "r"(32u) : "memory");
        asm volatile("mbarrier.init.shared.b64 [%0], %1;"
                     :: "r"(smem_u32(&rbar)), "r"(96u) : "memory");
    }
    __syncthreads();
    asm volatile("barrier.cluster.arrive.aligned;" ::: "memory");
    asm volatile("barrier.cluster.wait.aligned;" ::: "memory");

    // --- addresses. Remote senders: ks>=1, even jj -> peer (r+ks)&3.
    //     Local writers: ks==0, even jj -> own hbuf. ---
    uint32_t raddr0 = 0, raddr1 = 0, rmbar = 0;
    uint32_t laddr0 = 0, laddr1 = 0;
    {
        uint32_t off = (uint32_t)r * 128 + (uint32_t)(jj & ~1) * 2;
        laddr0 = smem_u32(&hbuf[0][0]) + off;
        laddr1 = smem_u32(&hbuf[1][0]) + off;
        if (ks >= 1) {
            uint32_t trg = (uint32_t)((r + ks) & 3);
            uint32_t lm = smem_u32(&rbar);
            asm("mapa.shared::cluster.u32 %0, %1, %2;" : "=r"(raddr0) : "r"(laddr0), "r"(trg));
            asm("mapa.shared::cluster.u32 %0, %1, %2;" : "=r"(raddr1) : "r"(laddr1), "r"(trg));
            asm("mapa.shared::cluster.u32 %0, %1, %2;" : "=r"(rmbar)  : "r"(lm), "r"(trg));
        }
    }

    float c = 0.f;
    size_t xgbase = (size_t)b * T_ * G_ + (size_t)r * 256 + (size_t)ks * 64 + jj;
    size_t obase  = (size_t)b * T_ * H_ + (size_t)r * 64 + jj;
    const uint32_t lmb = smem_u32(&lbar);
    const uint32_t rmb = smem_u32(&rbar);

    float xg_cur = g_xg[xgbase];
    float xg_nx  = g_xg[xgbase + G_];

    for (int t = 0; t < T_; t++) {
        // prefetch xg two steps ahead (independent)
        float xg_n2 = 0.f;
        if (t + 2 < T_) xg_n2 = __ldg(&g_xg[xgbase + (size_t)(t + 2) * G_]);

        // --- wait local own-slice h (fast: local arrives from prev step) ---
        if (t > 0) {
            uint32_t par = (t - 1) & 1;
            asm volatile(
                "{\n\t.reg .pred p;\n"
                "LW%=:\n\t"
                "mbarrier.try_wait.parity.acquire.cta.shared::cta.b64 p, [%0], %1, 0x989680;\n\t"
                "@!p bra LW%=;\n\t}"
                :: "r"(lmb), "r"(par) : "memory");
        }

        const uint4* hv = (const uint4*)hbuf[t & 1];
        half2 a[4][2];
        #pragma unroll
        for (int g = 0; g < 4; g++) {
            a[g][0] = __floats2half2_rn(0.f, 0.f);
            a[g][1] = __floats2half2_rn(0.f, 0.f);
        }

        // --- own-slice chunk (si=0): hides remote flight ---
        {
            int bidx = r * 8 + ks * 2;
            uint4 h0 = hv[bidx], h1 = hv[bidx + 1];
            half2 hh[8];
            *(uint4*)&hh[0] = h0; *(uint4*)&hh[4] = h1;
            #pragma unroll
            for (int g = 0; g < 4; g++) {
                #pragma unroll
                for (int i = 0; i < 4; i++)
                    a[g][0] = __hfma2(w2[g * 8 + i], hh[i], a[g][0]);
                #pragma unroll
                for (int i = 4; i < 8; i++)
                    a[g][1] = __hfma2(w2[g * 8 + i], hh[i], a[g][1]);
            }
        }

        // --- wait remote slices ---
        if (t > 0) {
            uint32_t par = (t - 1) & 1;
            asm volatile(
                "{\n\t.reg .pred p;\n"
                "RW%=:\n\t"
                "mbarrier.try_wait.parity.acquire.cluster.shared::cta.b64 p, [%0], %1, 0x989680;\n\t"
                "@!p bra RW%=;\n\t}"
                :: "r"(rmb), "r"(par) : "memory");
        }

        // --- remote slices (si=1..3) ---
        #pragma unroll
        for (int si = 1; si < 4; si++) {
            int bidx = (((r + si) & 3) * 8) + ks * 2;
            uint4 h0 = hv[bidx], h1 = hv[bidx + 1];
            half2 hh[8];
            *(uint4*)&hh[0] = h0; *(uint4*)&hh[4] = h1;
            #pragma unroll
            for (int g = 0; g < 4; g++) {
                #pragma unroll
                for (int i = 0; i < 4; i++)
                    a[g][0] = __hfma2(w2[(si * 4 + g) * 8 + i], hh[i], a[g][0]);
                #pragma unroll
                for (int i = 4; i < 8; i++)
                    a[g][1] = __hfma2(w2[(si * 4 + g) * 8 + i], hh[i], a[g][1]);
            }
        }

        // --- fp32 partials, fold xg (this lane's gate = ks) ---
        float partial[4];
        #pragma unroll
        for (int g = 0; g < 4; g++) {
            float2 f0 = __half22float2(a[g][0]);
            float2 f1 = __half22float2(a[g][1]);
            partial[g] = (f0.x + f0.y) + (f1.x + f1.y);
        }
        partial[ks] += xg_cur;

        // --- 3-shfl transpose-reduce: lane ks ends with total of gate ks ---
        float s_my, s_alt;
        {
            float send1 = partial[ks ^ 1];
            float t1 = __shfl_xor_sync(0xffffffffu, send1, 1);   // partner's partial[my gate]
            s_my = partial[ks] + t1;
            float send2 = partial[ks ^ 3];
            float t2 = __shfl_xor_sync(0xffffffffu, send2, 1);   // partner's partial[ks^2]
            s_alt = partial[ks ^ 2] + t2;                         // pair-sum of gate ks^2
        }
        float t3 = __shfl_xor_sync(0xffffffffu, s_alt, 2);       // other pair's sum of gate ks
        float mypre = s_my + t3;

        // --- split activation: lane ks computes gate ks (ks==2 -> tanh) ---
        float av;
        if (ks == 2) {
            float e = __expf(mypre + mypre);
            av = 1.f - __fdividef(2.f, e + 1.f);
        } else {
            av = __fdividef(1.f, 1.f + __expf(-mypre));
        }

        // --- 3-shfl gather of the 4 activations within the quad ---
        float v1 = __shfl_xor_sync(0xffffffffu, av, 1);
        float g_lo = (ks & 1) ? v1 : av;
        float g_hi = (ks & 1) ? av : v1;
        float r_lo = __shfl_xor_sync(0xffffffffu, g_lo, 2);
        float r_hi = __shfl_xor_sync(0xffffffffu, g_hi, 2);
        float gi = (ks < 2) ? g_lo : r_lo;
        float gf = (ks < 2) ? g_hi : r_hi;
        float gg = (ks < 2) ? r_lo : g_lo;
        float go = (ks < 2) ? r_hi : g_hi;

        // --- replicated c/h within the quad ---
        c = gf * c + gi * gg;
        float e = __expf(c + c);
        float th = 1.f - __fdividef(2.f, e + 1.f);
        float h = go * th;
        half h16 = __float2half_rn(h);
        uint32_t hu = (uint32_t)__half_as_ushort(h16);

        if (ks == 0) out[obase + (size_t)t * H_] = h;   // exact fp32 output

        // --- pack pair (jj, jj^1) -> u32; fire-and-forget sends (no drain) ---
        uint32_t v01 = hu | (__shfl_xor_sync(0xffffffffu, hu, 4) << 16);
        if (t < T_ - 1 && (jj & 1) == 0) {
            if (ks == 0) {
                uint32_t dst = ((t & 1) == 0) ? laddr1 : laddr0;
                asm volatile("st.shared.u32 [%0], %1;" :: "r"(dst), "r"(v01) : "memory");
                asm volatile("mbarrier.arrive.release.cta.shared::cta.b64 _, [%0];"
                             :: "r"(lmb) : "memory");
            } else {
                uint32_t dst = ((t & 1) == 0) ? raddr1 : raddr0;
                asm volatile("st.shared::cluster.u32 [%0], %1;"
                             :: "r"(dst), "r"(v01) : "memory");
                asm volatile("mbarrier.arrive.release.cluster.shared::cluster.b64 _, [%0];"
                             :: "r"(rmbar) : "memory");
            }
        }

        xg_cur = xg_nx;
        xg_nx = xg_n2;
    }

    asm volatile("barrier.cluster.arrive.aligned;" ::: "memory");
    asm volatile("barrier.cluster.wait.aligned;" ::: "memory");
}

// ---------------------------------------------------------------------------
extern "C" void kernel_launch(void* const* d_in, const int* in_sizes, int n_in,
                              void* d_out, int out_size) {
    const float* x    = (const float*)d_in[0];
    const float* w_ih = (const float*)d_in[1];
    const float* w_hh = (const float*)d_in[2];
    const float* b_ih = (const float*)d_in[3];
    const float* b_hh = (const float*)d_in[4];
    float* out = (float*)d_out;

    const int smem = 2 * 128 * ASTRIDE * (int)sizeof(half);  // 135168
    cudaFuncSetAttribute(gemm_kernel, cudaFuncAttributeMaxDynamicSharedMemorySize, smem);
    gemm_kernel<<<dim3(8, 512), 256, smem>>>(x, w_ih, b_ih, b_hh);

    lstm_kernel<<<128, 256>>>(w_hh, out);
}

// round 17
// speedup vs baseline: 1.7166x; 1.7166x over previous
#include <cuda_runtime.h>
#include <cuda_fp16.h>
#include <stdint.h>

#define B_   32
#define T_   2048
#define D_   256
#define H_   256
#define G_   1024   // 4*H

// Scratch: permuted input-gate preactivations [B,T,1024] fp32 (includes both biases)
__device__ float g_xg[(size_t)B_ * T_ * G_];

// Column permutation used everywhere:
//   stored col n = r*256 + g*64 + jj  <->  original gate row = g*256 + r*64 + jj

// ---------------------------------------------------------------------------
// Phase 1: xg[m][n] = sum_k relu(x[m][k]) * W_ih[orig(n)][k] + b_ih + b_hh
// fp16 mma.sync m16n8k16, fp32 accumulate. CTA tile 128x128, K=256 one-shot.
// ---------------------------------------------------------------------------
#define ASTRIDE 264   // halves per smem row (4-bank shift per row -> conflict free)

__global__ __launch_bounds__(256) void gemm_kernel(const float* __restrict__ x,
                                                   const float* __restrict__ w_ih,
                                                   const float* __restrict__ b_ih,
                                                   const float* __restrict__ b_hh) {
    extern __shared__ half sm[];
    half* As = sm;                    // [128][ASTRIDE]
    half* Bs = sm + 128 * ASTRIDE;    // [128][ASTRIDE]

    int tid = threadIdx.x;
    int n0 = blockIdx.x * 128;
    int m0 = blockIdx.y * 128;

    for (int i = tid; i < 128 * 64; i += 256) {
        int row = i >> 6, c4 = i & 63;
        float4 v = *(const float4*)(x + (size_t)(m0 + row) * 256 + c4 * 4);
        v.x = fmaxf(v.x, 0.f); v.y = fmaxf(v.y, 0.f);
        v.z = fmaxf(v.z, 0.f); v.w = fmaxf(v.w, 0.f);
        *(half2*)(As + row * ASTRIDE + c4 * 4)     = __floats2half2_rn(v.x, v.y);
        *(half2*)(As + row * ASTRIDE + c4 * 4 + 2) = __floats2half2_rn(v.z, v.w);
    }
    for (int i = tid; i < 128 * 64; i += 256) {
        int row = i >> 6, c4 = i & 63;
        int ng = n0 + row;
        int r = ng >> 8, rem = ng & 255, g = rem >> 6, jj = rem & 63;
        int orig = g * 256 + r * 64 + jj;
        float4 v = *(const float4*)(w_ih + (size_t)orig * 256 + c4 * 4);
        *(half2*)(Bs + row * ASTRIDE + c4 * 4)     = __floats2half2_rn(v.x, v.y);
        *(half2*)(Bs + row * ASTRIDE + c4 * 4 + 2) = __floats2half2_rn(v.z, v.w);
    }
    __syncthreads();

    int lane = tid & 31, warp = tid >> 5;
    int wm = warp & 3;
    int wn = warp >> 2;
    int gr = lane >> 2;
    int qc = (lane & 3) * 2;

    float acc[2][8][4];
    #pragma unroll
    for (int a = 0; a < 2; a++)
        #pragma unroll
        for (int b = 0; b < 8; b++)
            #pragma unroll
            for (int c = 0; c < 4; c++) acc[a][b][c] = 0.f;

    #pragma unroll
    for (int k0 = 0; k0 < 256; k0 += 16) {
        uint32_t af[2][4];
        #pragma unroll
        for (int mt = 0; mt < 2; mt++) {
            int rb = wm * 32 + mt * 16 + gr;
            af[mt][0] = *(const uint32_t*)(As + rb * ASTRIDE + k0 + qc);
            af[mt][1] = *(const uint32_t*)(As + (rb + 8) * ASTRIDE + k0 + qc);
            af[mt][2] = *(const uint32_t*)(As + rb * ASTRIDE + k0 + qc + 8);
            af[mt][3] = *(const uint32_t*)(As + (rb + 8) * ASTRIDE + k0 + qc + 8);
        }
        #pragma unroll
        for (int nt = 0; nt < 8; nt++) {
            int nr = wn * 64 + nt * 8 + gr;
            uint32_t b0 = *(const uint32_t*)(Bs + nr * ASTRIDE + k0 + qc);
            uint32_t b1 = *(const uint32_t*)(Bs + nr * ASTRIDE + k0 + qc + 8);
            #pragma unroll
            for (int mt = 0; mt < 2; mt++) {
                asm volatile(
                    "mma.sync.aligned.m16n8k16.row.col.f32.f16.f16.f32 "
                    "{%0,%1,%2,%3}, {%4,%5,%6,%7}, {%8,%9}, {%0,%1,%2,%3};\n"
                    : "+f"(acc[mt][nt][0]), "+f"(acc[mt][nt][1]),
                      "+f"(acc[mt][nt][2]), "+f"(acc[mt][nt][3])
                    : "r"(af[mt][0]), "r"(af[mt][1]), "r"(af[mt][2]), "r"(af[mt][3]),
                      "r"(b0), "r"(b1));
            }
        }
    }

    #pragma unroll
    for (int mt = 0; mt < 2; mt++) {
        #pragma unroll
        for (int nt = 0; nt < 8; nt++) {
            int col = n0 + wn * 64 + nt * 8 + qc;
            int rr = col >> 8, rem = col & 255, gg = rem >> 6, jjc = rem & 63;
            int orig = gg * 256 + rr * 64 + jjc;
            float bv0 = b_ih[orig] + b_hh[orig];
            float bv1 = b_ih[orig + 1] + b_hh[orig + 1];
            int row = m0 + wm * 32 + mt * 16 + gr;
            float2 v0 = {acc[mt][nt][0] + bv0, acc[mt][nt][1] + bv1};
            float2 v1 = {acc[mt][nt][2] + bv0, acc[mt][nt][3] + bv1};
            *(float2*)(g_xg + (size_t)row * G_ + col)       = v0;
            *(float2*)(g_xg + (size_t)(row + 8) * G_ + col) = v1;
        }
    }
}

// ---------------------------------------------------------------------------
// Phase 2: persistent LSTM scan. One 4-CTA cluster per batch element.
// R3-best structure with ONE __syncthreads per step:
//   wait lbar (64 local arrives: q0's own-slice h publication, acquire.cta)
//   own-slice FMA                      <- hides remote flight
//   wait rbar (192 remote arrives, acquire.cluster)
//   remote FMA -> reduce + xg -> activation -> act[t&1][tid]
//   __syncthreads                      <- act exchange (only bar; sends are
//                                         ~600 cyc old by now -> no drain)
//   replicated c/h in all threads
//   q0: fp32 out + local hbuf STS + arrive.release.cta(lbar)
//   q>=1: fire-and-forget u16 DSMEM send + arrive.release.cluster(rbar)
// ---------------------------------------------------------------------------
__device__ __forceinline__ uint32_t smem_u32(const void* p) {
    return (uint32_t)__cvta_generic_to_shared(p);
}

__global__ __launch_bounds__(256, 1) __cluster_dims__(4, 1, 1)
void lstm_kernel(const float* __restrict__ w_hh, float* __restrict__ out) {
    __shared__ __align__(16) half hbuf[2][256];   // double-buffered h (fp16)
    __shared__ float act[2][256];                 // double-buffered activations
    __shared__ __align__(8) unsigned long long lbar;
    __shared__ __align__(8) unsigned long long rbar;

    int tid = threadIdx.x;
    int b = blockIdx.x >> 2;
    int r = blockIdx.x & 3;
    int q = tid >> 6;        // gate quadrant 0..3 (i,f,g,o)
    int jj = tid & 63;       // h index within this CTA's slice

    // --- load this thread's weight row (rotated by own slice) into regs ---
    int orig = q * 256 + r * 64 + jj;
    const float4* wr = (const float4*)(w_hh + (size_t)orig * 256);
    half2 w2[128];
    #pragma unroll
    for (int i = 0; i < 64; i++) {
        float4 v = wr[(16 * r + i) & 63];   // rotation: w2[2i] covers h[(64r+4i)%256..]
        w2[2 * i]     = __floats2half2_rn(v.x, v.y);
        w2[2 * i + 1] = __floats2half2_rn(v.z, v.w);
    }

    // --- init smem ---
    ((uint32_t*)hbuf)[tid] = 0u;   // both h buffers zeroed
    if (tid == 0) {
        asm volatile("mbarrier.init.shared.b64 [%0], %1;"
                     :: "r"(smem_u32(&lbar)), "r"(64u) : "memory");   // q0 local
        asm volatile("mbarrier.init.shared.b64 [%0], %1;"
                     :: "r"(smem_u32(&rbar)), "r"(192u) : "memory");  // 3 peers x 64
    }
    __syncthreads();
    asm volatile("barrier.cluster.arrive.aligned;" ::: "memory");
    asm volatile("barrier.cluster.wait.aligned;" ::: "memory");

    // --- remote DSMEM addresses (q>=1 threads send u16 to peer (r+q)&3) ---
    uint32_t raddr0 = 0, raddr1 = 0, rmbar = 0;
    if (q >= 1) {
        uint32_t trg = (uint32_t)((r + q) & 3);
        uint32_t off = (uint32_t)r * 128 + (uint32_t)jj * 2;
        uint32_t l0 = smem_u32(&hbuf[0][0]) + off;
        uint32_t l1 = smem_u32(&hbuf[1][0]) + off;
        uint32_t lm = smem_u32(&rbar);
        asm("mapa.shared::cluster.u32 %0, %1, %2;" : "=r"(raddr0) : "r"(l0), "r"(trg));
        asm("mapa.shared::cluster.u32 %0, %1, %2;" : "=r"(raddr1) : "r"(l1), "r"(trg));
        asm("mapa.shared::cluster.u32 %0, %1, %2;" : "=r"(rmbar)  : "r"(lm), "r"(trg));
    }

    float c = 0.f;
    size_t xgbase = (size_t)b * T_ * G_ + (size_t)r * 256 + tid;
    size_t obase  = (size_t)b * T_ * H_ + (size_t)r * 64 + jj;
    const uint32_t lmb = smem_u32(&lbar);
    const uint32_t rmb = smem_u32(&rbar);
    const int ubase = 8 * r;   // own-slice uint4 base index in hbuf

    float xg_cur = g_xg[xgbase];
    float xg_nx  = g_xg[xgbase + G_];

    for (int t = 0; t < T_; t++) {
        // prefetch xg two steps ahead (independent)
        float xg_n2 = 0.f;
        if (t + 2 < T_) xg_n2 = __ldg(&g_xg[xgbase + (size_t)(t + 2) * G_]);

        // --- wait local own-slice publication (fast local wakeup) ---
        if (t > 0) {
            uint32_t par = (t - 1) & 1;
            asm volatile(
                "{\n\t.reg .pred p;\n"
                "QW%=:\n\t"
                "mbarrier.try_wait.parity.acquire.cta.shared::cta.b64 p, [%0], %1, 0x989680;\n\t"
                "@!p bra QW%=;\n\t}"
                :: "r"(lmb), "r"(par) : "memory");
        }

        const uint4* hv = (const uint4*)hbuf[t & 1];
        half2 a[8];
        #pragma unroll
        for (int i = 0; i < 8; i++) a[i] = __floats2half2_rn(0.f, 0.f);

        // --- own-slice chunk first: hides remote flight ---
        #pragma unroll
        for (int u = 0; u < 8; u++) {
            uint4 h4 = hv[(ubase + u) & 31];
            int j = 4 * u;
            a[(j + 0) & 7] = __hfma2(w2[j + 0], *(half2*)&h4.x, a[(j + 0) & 7]);
            a[(j + 1) & 7] = __hfma2(w2[j + 1], *(half2*)&h4.y, a[(j + 1) & 7]);
            a[(j + 2) & 7] = __hfma2(w2[j + 2], *(half2*)&h4.z, a[(j + 2) & 7]);
            a[(j + 3) & 7] = __hfma2(w2[j + 3], *(half2*)&h4.w, a[(j + 3) & 7]);
        }

        // --- wait remote slices (sent at end of step t-1) ---
        if (t > 0) {
            uint32_t par = (t - 1) & 1;
            asm volatile(
                "{\n\t.reg .pred p;\n"
                "LW%=:\n\t"
                "mbarrier.try_wait.parity.acquire.cluster.shared::cta.b64 p, [%0], %1, 0x989680;\n\t"
                "@!p bra LW%=;\n\t}"
                :: "r"(rmb), "r"(par) : "memory");
        }

        // --- remote chunks ---
        #pragma unroll
        for (int u = 8; u < 32; u++) {
            uint4 h4 = hv[(ubase + u) & 31];
            int j = 4 * u;
            a[(j + 0) & 7] = __hfma2(w2[j + 0], *(half2*)&h4.x, a[(j + 0) & 7]);
            a[(j + 1) & 7] = __hfma2(w2[j + 1], *(half2*)&h4.y, a[(j + 1) & 7]);
            a[(j + 2) & 7] = __hfma2(w2[j + 2], *(half2*)&h4.z, a[(j + 2) & 7]);
            a[(j + 3) & 7] = __hfma2(w2[j + 3], *(half2*)&h4.w, a[(j + 3) & 7]);
        }

        float s = 0.f;
        #pragma unroll
        for (int i = 0; i < 8; i++) {
            float2 fv = __half22float2(a[i]);
            s += fv.x + fv.y;
        }
        float pre = s + xg_cur;

        // --- activation (q==2 -> tanh, else sigmoid) ---
        float av;
        if (q == 2) {
            float e = __expf(pre + pre);
            av = 1.f - __fdividef(2.f, e + 1.f);
        } else {
            av = __fdividef(1.f, 1.f + __expf(-pre));
        }
        act[t & 1][tid] = av;
        __syncthreads();   // the only bar.sync per step (act exchange)

        // --- replicated c/h update in ALL threads (identical fp32 per jj) ---
        const float* ap = act[t & 1];
        float gi = ap[jj], gf = ap[64 + jj], gg = ap[128 + jj], go = ap[192 + jj];
        c = gf * c + gi * gg;
        float e = __expf(c + c);
        float th = 1.f - __fdividef(2.f, e + 1.f);
        float h = go * th;
        half h16 = __float2half_rn(h);

        if (q == 0) {
            out[obase + (size_t)t * H_] = h;              // exact fp32 output
            if (t < T_ - 1) {
                hbuf[(t + 1) & 1][r * 64 + jj] = h16;     // local own slice
                asm volatile("mbarrier.arrive.release.cta.shared::cta.b64 _, [%0];"
                             :: "r"(lmb) : "memory");
            }
        } else if (t < T_ - 1) {
            // fire-and-forget u16 send to peer's next buffer
            uint32_t dst = ((t & 1) == 0) ? raddr1 : raddr0;
            asm volatile("st.shared::cluster.u16 [%0], %1;"
                         :: "r"(dst), "h"(__half_as_ushort(h16)) : "memory");
            asm volatile("mbarrier.arrive.release.cluster.shared::cluster.b64 _, [%0];"
                         :: "r"(rmbar) : "memory");
        }

        xg_cur = xg_nx;
        xg_nx = xg_n2;
    }

    asm volatile("barrier.cluster.arrive.aligned;" ::: "memory");
    asm volatile("barrier.cluster.wait.aligned;" ::: "memory");
}

// ---------------------------------------------------------------------------
extern "C" void kernel_launch(void* const* d_in, const int* in_sizes, int n_in,
                              void* d_out, int out_size) {
    const float* x    = (const float*)d_in[0];
    const float* w_ih = (const float*)d_in[1];
    const float* w_hh = (const float*)d_in[2];
    const float* b_ih = (const float*)d_in[3];
    const float* b_hh = (const float*)d_in[4];
    float* out = (float*)d_out;

    const int smem = 2 * 128 * ASTRIDE * (int)sizeof(half);  // 135168
    cudaFuncSetAttribute(gemm_kernel, cudaFuncAttributeMaxDynamicSharedMemorySize, smem);
    gemm_kernel<<<dim3(8, 512), 256, smem>>>(x, w_ih, b_ih, b_hh);

    lstm_kernel<<<128, 256>>>(w_hh, out);
}